// round 9
// baseline (speedup 1.0000x reference)
#include <cuda_runtime.h>
#include <cuda_bf16.h>

#define B_DIM 64
#define T_DIM 512
#define M_DIM 512
#define PAD_INDEX 1
#define LAMBDA1 0.02f
#define LAMBDA2 0.1f

__global__ void zero_out_kernel(float* out) { out[0] = 0.0f; }

// Non-CSE-able reload: the line is hot in L1 (fetched by the pipelined
// prefetch 2 iterations earlier); asm volatile prevents the compiler from
// keeping the original registers alive instead.
__device__ __forceinline__ float4 ldg_reload(const float4* p) {
    float4 v;
    asm volatile("ld.global.nc.v4.f32 {%0,%1,%2,%3}, [%4];"
                 : "=f"(v.x), "=f"(v.y), "=f"(v.z), "=f"(v.w)
                 : "l"(p));
    return v;
}

// One CTA per t. 256 threads = 8 warps; warp w handles b = w + 8k, k=0..7.
// Each lane holds 16 floats of the 512-wide row: float4 chunks at
// float4-index (lane + 32c), c=0..3.
//
// Depth-3 mixed pipeline: rows for k+1 and k+2 are in flight while k is
// processed. Row registers are freed right after squaring (the accumulate
// re-reads the row from L1 via ldg_reload), which is what makes depth-3
// fit in the 128-reg / 2-CTA budget.
__global__ __launch_bounds__(256, 2) void vmf_loss_kernel(
    const float* __restrict__ outputs,    // [B,T,M]
    const int*   __restrict__ targets,    // [B,T]
    const float* __restrict__ embedding,  // [V,M]
    float* __restrict__ out)
{
    const int t    = blockIdx.x;
    const int tid  = threadIdx.x;
    const int w    = tid >> 5;
    const int lane = tid & 31;

    float acc_o[16];
    float acc_t[16];
#pragma unroll
    for (int i = 0; i < 16; i++) { acc_o[i] = 0.0f; acc_t[i] = 0.0f; }

    float sum_a   = 0.0f;   // lane-uniform
    float n_valid = 0.0f;   // lane-uniform

    int tg[8];
#pragma unroll
    for (int k = 0; k < 8; k++)
        tg[k] = __ldg(&targets[(w + 8 * k) * T_DIM + t]);

    // row base pointers (float4-granular)
    const float4* orow[8];
    const float4* erow[8];
#pragma unroll
    for (int k = 0; k < 8; k++) {
        orow[k] = (const float4*)(outputs + ((size_t)(w + 8 * k) * T_DIM + t) * M_DIM);
        erow[k] = (const float4*)(embedding + (size_t)tg[k] * M_DIM);
    }

    // ---- prologue: slots 0,1 <- rows 0,1 ----
    float4 bo[2][4], be[2][4];
#pragma unroll
    for (int s = 0; s < 2; s++) {
#pragma unroll
        for (int c = 0; c < 4; c++) bo[s][c] = __ldg(&orow[s][lane + 32 * c]);
#pragma unroll
        for (int c = 0; c < 4; c++) be[s][c] = __ldg(&erow[s][lane + 32 * c]);
    }

#pragma unroll
    for (int k = 0; k < 8; k++) {
        const int slot = k & 1;

        // ---- per-lane squares (last use of the slot registers) ----
        float ss = 0.0f, es = 0.0f;
#pragma unroll
        for (int c = 0; c < 4; c++) {
            const float4 o = bo[slot][c];
            const float4 e = be[slot][c];
            ss += o.x * o.x + o.y * o.y + o.z * o.z + o.w * o.w;
            es += e.x * e.x + e.y * e.y + e.z * e.z + e.w * e.w;
        }

        // ---- refill the freed slot with row k+2 ----
        if (k + 2 < 8) {
#pragma unroll
            for (int c = 0; c < 4; c++)
                bo[slot][c] = __ldg(&orow[k + 2][lane + 32 * c]);
#pragma unroll
            for (int c = 0; c < 4; c++)
                be[slot][c] = __ldg(&erow[k + 2][lane + 32 * c]);
        }

        // ---- interleaved butterfly reductions ----
#pragma unroll
        for (int off = 16; off > 0; off >>= 1) {
            ss += __shfl_xor_sync(0xffffffffu, ss, off);
            es += __shfl_xor_sync(0xffffffffu, es, off);
        }

        const float inv_o = rsqrtf(fmaxf(ss, 1e-24f));
        const float mask  = (tg[k] != PAD_INDEX) ? 1.0f : 0.0f;
        const float inv_e = mask * rsqrtf(fmaxf(es, 1e-24f));
        n_valid += mask;

        // ---- accumulate via L1-hot reloads (off the critical path) ----
#pragma unroll
        for (int c = 0; c < 4; c++) {
            const float4 o = ldg_reload(&orow[k][lane + 32 * c]);
            acc_o[c * 4 + 0] += o.x * inv_o;
            acc_o[c * 4 + 1] += o.y * inv_o;
            acc_o[c * 4 + 2] += o.z * inv_o;
            acc_o[c * 4 + 3] += o.w * inv_o;
        }
#pragma unroll
        for (int c = 0; c < 4; c++) {
            const float4 e = ldg_reload(&erow[k][lane + 32 * c]);
            acc_t[c * 4 + 0] += e.x * inv_e;
            acc_t[c * 4 + 1] += e.y * inv_e;
            acc_t[c * 4 + 2] += e.z * inv_e;
            acc_t[c * 4 + 3] += e.w * inv_e;
        }

        // logC_m(kappa), v = M/2-1 = 255:
        //   sqrt(256^2 + z^2) - 254*log(254 + sqrt(254^2 + z^2))
        const float kappa = sqrtf(ss);
        const float logc  = sqrtf(65536.0f + ss)
                          - 254.0f * __logf(254.0f + sqrtf(64516.0f + ss));
        sum_a += (-logc + LAMBDA1 * kappa);
    }

    // ---- block combine: s_out[m], s_trg[m], dot ----
    __shared__ float4 shv[8 * 128];   // 16 KB, reused for both passes
    __shared__ float  sh_dot[8];
    __shared__ float  sh_a[8];
    __shared__ float  sh_nv[8];

    float* shf = (float*)shv;   // [warp][512] floats

    // pass A: s_out
#pragma unroll
    for (int c = 0; c < 4; c++)
        shv[w * 128 + lane + 32 * c] =
            make_float4(acc_o[c * 4 + 0], acc_o[c * 4 + 1],
                        acc_o[c * 4 + 2], acc_o[c * 4 + 3]);
    __syncthreads();

    // thread owns m = tid and m = tid + 256
    float so0 = 0.0f, so1 = 0.0f;
#pragma unroll
    for (int ww = 0; ww < 8; ww++) {
        so0 += shf[ww * 512 + tid];
        so1 += shf[ww * 512 + tid + 256];
    }
    __syncthreads();

    // pass B: s_trg
#pragma unroll
    for (int c = 0; c < 4; c++)
        shv[w * 128 + lane + 32 * c] =
            make_float4(acc_t[c * 4 + 0], acc_t[c * 4 + 1],
                        acc_t[c * 4 + 2], acc_t[c * 4 + 3]);
    __syncthreads();

    float st0 = 0.0f, st1 = 0.0f;
#pragma unroll
    for (int ww = 0; ww < 8; ww++) {
        st0 += shf[ww * 512 + tid];
        st1 += shf[ww * 512 + tid + 256];
    }

    float dp = so0 * st0 + so1 * st1;
#pragma unroll
    for (int off = 16; off > 0; off >>= 1)
        dp += __shfl_xor_sync(0xffffffffu, dp, off);

    if (lane == 0) {
        sh_dot[w] = dp;
        sh_a[w]   = sum_a;
        sh_nv[w]  = n_valid;
    }
    __syncthreads();

    if (tid == 0) {
        float dot = 0.0f, sa = 0.0f, nv = 0.0f;
#pragma unroll
        for (int i = 0; i < 8; i++) {
            dot += sh_dot[i];
            sa  += sh_a[i];
            nv  += sh_nv[i];
        }
        const float val = nv * sa - LAMBDA2 * dot;
        atomicAdd(out, val);
    }
}

extern "C" void kernel_launch(void* const* d_in, const int* in_sizes, int n_in,
                              void* d_out, int out_size) {
    const float* outputs   = (const float*)d_in[0];
    const int*   targets   = (const int*)d_in[1];
    const float* embedding = (const float*)d_in[2];
    float* out = (float*)d_out;

    zero_out_kernel<<<1, 1>>>(out);
    vmf_loss_kernel<<<T_DIM, 256>>>(outputs, targets, embedding, out);
}